// round 3
// baseline (speedup 1.0000x reference)
#include <cuda_runtime.h>
#include <cuda_fp16.h>
#include <cstdint>

// ============================================================================
// Problem constants (shapes fixed by setup_inputs)
// ============================================================================
static constexpr int BD   = 32;    // batch
static constexpr int VV   = 4;     // views
static constexpr int PP   = 784;   // patches
static constexpr int DD   = 768;   // model dim
static constexpr int TT   = VV * PP;           // 3136
static constexpr size_t TOK = (size_t)BD * TT; // 100352 tokens
static constexpr int HH   = 8;
static constexpr int DH   = 96;

// ============================================================================
// PTX helpers (portable sm_80+ subset only — NO tcgen05 / "a"-features)
// ============================================================================
__device__ __forceinline__ uint32_t smem_to_u32(const void* smem_ptr) {
    uint32_t addr;
    asm("{ .reg .u64 tmp; cvta.to.shared.u64 tmp, %1; cvt.u32.u64 %0, tmp; }"
        : "=r"(addr) : "l"(smem_ptr));
    return addr;
}

__device__ __forceinline__ void cp_async16(uint32_t saddr, const void* gptr) {
    asm volatile("cp.async.cg.shared.global [%0], [%1], 16;"
                 :: "r"(saddr), "l"(gptr) : "memory");
}
__device__ __forceinline__ void cp_commit() {
    asm volatile("cp.async.commit_group;" ::: "memory");
}
template<int N>
__device__ __forceinline__ void cp_wait() {
    asm volatile("cp.async.wait_group %0;" :: "n"(N) : "memory");
}

__device__ __forceinline__ void ldsm_x4(uint32_t* r, uint32_t addr) {
    asm volatile("ldmatrix.sync.aligned.m8n8.x4.shared.b16 {%0,%1,%2,%3}, [%4];"
                 : "=r"(r[0]), "=r"(r[1]), "=r"(r[2]), "=r"(r[3]) : "r"(addr));
}

__device__ __forceinline__ void mma16816(float* c, const uint32_t* a, const uint32_t* b) {
    asm volatile(
        "mma.sync.aligned.m16n8k16.row.col.f32.f16.f16.f32 "
        "{%0,%1,%2,%3},{%4,%5,%6,%7},{%8,%9},{%0,%1,%2,%3};"
        : "+f"(c[0]), "+f"(c[1]), "+f"(c[2]), "+f"(c[3])
        : "r"(a[0]), "r"(a[1]), "r"(a[2]), "r"(a[3]), "r"(b[0]), "r"(b[1]));
}

// ============================================================================
// Device scratch (static __device__ arrays; cudaMalloc is forbidden)
// ============================================================================
__device__ __half g_h16 [TOK * DD];          // LN1 output (fp16)
__device__ __half g_qkv [TOK * 3 * DD];      // QKV (fp16)
__device__ __half g_o16 [TOK * DD];          // attention output (fp16)
__device__ float  g_x1  [TOK * DD];          // x + attn proj (fp32)
__device__ __half g_h2  [TOK * DD];          // LN2 output (fp16)
__device__ __half g_ffn [TOK * 4 * DD];      // gelu(ffn1) (fp16)
__device__ __half g_wqkv[3 * DD * DD];
__device__ __half g_wout[DD * DD];
__device__ __half g_w1  [4 * DD * DD];
__device__ __half g_w2  [DD * 4 * DD];

// ============================================================================
// fp32 -> fp16 weight conversion
// ============================================================================
__global__ void f2h_kernel(const float* __restrict__ in, __half* __restrict__ out, int n) {
    int i = blockIdx.x * blockDim.x + threadIdx.x;
    int stride = gridDim.x * blockDim.x;
    for (; i < n; i += stride) out[i] = __float2half(in[i]);
}

// ============================================================================
// LayerNorm: fp32 input -> fp16 output. One block (192 thr) per row of 768.
// ============================================================================
__global__ void __launch_bounds__(192) ln_kernel(
    const float* __restrict__ x, const float* __restrict__ w,
    const float* __restrict__ bb, __half* __restrict__ out)
{
    size_t row = blockIdx.x;
    int t = threadIdx.x;
    float4 v = reinterpret_cast<const float4*>(x + row * DD)[t];
    float s  = v.x + v.y + v.z + v.w;
    float ss = v.x*v.x + v.y*v.y + v.z*v.z + v.w*v.w;
    #pragma unroll
    for (int off = 16; off; off >>= 1) {
        s  += __shfl_xor_sync(0xffffffffu, s,  off);
        ss += __shfl_xor_sync(0xffffffffu, ss, off);
    }
    __shared__ float rs_[6], rss_[6];
    int wi = t >> 5, ln = t & 31;
    if (ln == 0) { rs_[wi] = s; rss_[wi] = ss; }
    __syncthreads();
    float tot = 0.f, tot2 = 0.f;
    #pragma unroll
    for (int i = 0; i < 6; ++i) { tot += rs_[i]; tot2 += rss_[i]; }
    float mu  = tot * (1.0f / DD);
    float var = tot2 * (1.0f / DD) - mu * mu;
    float rstd = rsqrtf(var + 1e-5f);
    float4 wv = reinterpret_cast<const float4*>(w)[t];
    float4 bv = reinterpret_cast<const float4*>(bb)[t];
    __half2* op = reinterpret_cast<__half2*>(out + row * DD) + 2 * t;
    op[0] = __floats2half2_rn((v.x - mu) * rstd * wv.x + bv.x,
                              (v.y - mu) * rstd * wv.y + bv.y);
    op[1] = __floats2half2_rn((v.z - mu) * rstd * wv.z + bv.z,
                              (v.w - mu) * rstd * wv.w + bv.w);
}

// ============================================================================
// Cross-view attention: one warp per (b, p, head). V=4, dh=96 (3 dims/lane).
// ============================================================================
__global__ void __launch_bounds__(128) attn_kernel(
    const __half* __restrict__ qkv, __half* __restrict__ o)
{
    int wid = threadIdx.x >> 5, lane = threadIdx.x & 31;
    int g  = blockIdx.x * 4 + wid;     // (b,p,head) group id, < 200704
    int h  = g & 7;
    int bp = g >> 3;
    int b  = bp / PP, p = bp - b * PP;
    size_t rowbase = (size_t)b * TT + p;

    float q[4][3], k[4][3], vv[4][3];
    #pragma unroll
    for (int v = 0; v < 4; ++v) {
        const __half* r = qkv + (rowbase + (size_t)v * PP) * (3 * DD) + h * DH + lane;
        #pragma unroll
        for (int j = 0; j < 3; ++j) {
            q[v][j]  = __half2float(r[32 * j]);
            k[v][j]  = __half2float(r[DD + 32 * j]);
            vv[v][j] = __half2float(r[2 * DD + 32 * j]);
        }
    }
    float s[4][4];
    #pragma unroll
    for (int i = 0; i < 4; ++i) {
        #pragma unroll
        for (int j = 0; j < 4; ++j) {
            float acc = q[i][0]*k[j][0] + q[i][1]*k[j][1] + q[i][2]*k[j][2];
            #pragma unroll
            for (int off = 16; off; off >>= 1)
                acc += __shfl_xor_sync(0xffffffffu, acc, off);
            s[i][j] = acc * 0.1020620726f;   // 1/sqrt(96)
        }
    }
    #pragma unroll
    for (int i = 0; i < 4; ++i) {
        float m = fmaxf(fmaxf(s[i][0], s[i][1]), fmaxf(s[i][2], s[i][3]));
        float e0 = expf(s[i][0] - m), e1 = expf(s[i][1] - m);
        float e2 = expf(s[i][2] - m), e3 = expf(s[i][3] - m);
        float inv = 1.0f / (e0 + e1 + e2 + e3);
        __half* orow = o + (rowbase + (size_t)i * PP) * DD + h * DH + lane;
        #pragma unroll
        for (int j = 0; j < 3; ++j) {
            float ov = (e0 * vv[0][j] + e1 * vv[1][j] + e2 * vv[2][j] + e3 * vv[3][j]) * inv;
            orow[32 * j] = __float2half(ov);
        }
    }
}

// ============================================================================
// HMMA GEMM:  C[M,N] = A[M,K](fp16) @ W[N,K]^T(fp16) + bias, epilogue
//   EPI 0: out fp16 = acc + bias
//   EPI 1: out fp16 = gelu_exact(acc + bias)
//   EPI 2: out fp32 = acc + bias + resid
// CTA tile 128x128, BK=32, 256 thr (8 warps, 2x4 of 64x32 warp tiles),
// 3-stage cp.async pipeline, padded SMEM (ld = 40 halves, conflict-free).
// ============================================================================
static constexpr int LDS_   = 40;           // halves per smem row (32 + 8 pad)
static constexpr int OSTG   = 128 * LDS_;   // halves per operand per stage
static constexpr int NSTAGE = 3;
static constexpr int GSMEM  = NSTAGE * 2 * OSTG * 2; // bytes = 61440

template<int EPI>
__global__ void __launch_bounds__(256) gemm_mma(
    const __half* __restrict__ A, const __half* __restrict__ W,
    const float* __restrict__ bias, const float* __restrict__ resid,
    void* __restrict__ outp, int K, int Ntot)
{
    extern __shared__ __half smem[];
    int tid = threadIdx.x;
    int lane = tid & 31, wid = tid >> 5;
    int m0 = blockIdx.y * 128;
    int n0 = blockIdx.x * 128;
    int wm = (wid & 1) * 64;       // warp row offset in tile
    int wn = (wid >> 1) * 32;      // warp col offset in tile

    // ---- async prefetch of one K-chunk into stage s ----
    auto prefetch = [&](int kt, int s) {
        __half* st = smem + s * (2 * OSTG);
        int row = tid >> 2, cc = tid & 3;
        #pragma unroll
        for (int h = 0; h < 2; ++h) {
            int r = row + h * 64;
            cp_async16(smem_to_u32(st + r * LDS_ + cc * 8),
                       A + (size_t)(m0 + r) * K + kt * 32 + cc * 8);
            cp_async16(smem_to_u32(st + OSTG + r * LDS_ + cc * 8),
                       W + (size_t)(n0 + r) * K + kt * 32 + cc * 8);
        }
    };

    float c[4][4][4];
    #pragma unroll
    for (int i = 0; i < 4; ++i)
        #pragma unroll
        for (int j = 0; j < 4; ++j)
            #pragma unroll
            for (int r = 0; r < 4; ++r) c[i][j][r] = 0.f;

    int NK = K >> 5;
    prefetch(0, 0); cp_commit();
    prefetch(1, 1); cp_commit();

    // ldmatrix lane addressing (constant per thread)
    int a_r  = wm + (lane & 15);
    int a_k  = (lane >> 4) << 3;
    int b_n  = wn + (lane & 7) + ((lane >> 4) << 3);
    int b_k  = ((lane >> 3) & 1) << 3;

    #pragma unroll 1
    for (int kt = 0; kt < NK; ++kt) {
        cp_wait<1>();
        __syncthreads();
        if (kt + 2 < NK) prefetch(kt + 2, (kt + 2) % NSTAGE);
        cp_commit();

        const __half* sA = smem + (kt % NSTAGE) * (2 * OSTG);
        const __half* sB = sA + OSTG;
        #pragma unroll
        for (int ks = 0; ks < 2; ++ks) {
            uint32_t a[4][4], b[2][4];
            #pragma unroll
            for (int ma = 0; ma < 4; ++ma)
                ldsm_x4(a[ma], smem_to_u32(sA + (a_r + ma * 16) * LDS_ + ks * 16 + a_k));
            #pragma unroll
            for (int nb = 0; nb < 2; ++nb)
                ldsm_x4(b[nb], smem_to_u32(sB + (b_n + nb * 16) * LDS_ + ks * 16 + b_k));
            #pragma unroll
            for (int ma = 0; ma < 4; ++ma)
                #pragma unroll
                for (int na = 0; na < 4; ++na)
                    mma16816(c[ma][na], a[ma], b[na >> 1] + (na & 1) * 2);
        }
    }

    // ---- epilogue straight from registers ----
    #pragma unroll
    for (int ma = 0; ma < 4; ++ma) {
        #pragma unroll
        for (int na = 0; na < 4; ++na) {
            int row = m0 + wm + ma * 16 + (lane >> 2);
            int col = n0 + wn + na * 8 + ((lane & 3) << 1);
            float b0 = bias[col], b1 = bias[col + 1];
            #pragma unroll
            for (int h = 0; h < 2; ++h) {
                size_t off = (size_t)(row + h * 8) * Ntot + col;
                float v0 = c[ma][na][2 * h + 0] + b0;
                float v1 = c[ma][na][2 * h + 1] + b1;
                if (EPI == 1) {
                    v0 = 0.5f * v0 * (1.0f + erff(v0 * 0.70710678f));
                    v1 = 0.5f * v1 * (1.0f + erff(v1 * 0.70710678f));
                }
                if (EPI == 2) {
                    float2 r2 = *reinterpret_cast<const float2*>(resid + off);
                    float2 o2 = make_float2(v0 + r2.x, v1 + r2.y);
                    *reinterpret_cast<float2*>(reinterpret_cast<float*>(outp) + off) = o2;
                } else {
                    *reinterpret_cast<__half2*>(reinterpret_cast<__half*>(outp) + off) =
                        __floats2half2_rn(v0, v1);
                }
            }
        }
    }
}

// ============================================================================
// Host launch
// ============================================================================
extern "C" void kernel_launch(void* const* d_in, const int* in_sizes, int n_in,
                              void* d_out, int out_size)
{
    const float* x        = (const float*)d_in[0];
    // d_in[1] = num_views (scalar, fixed = 4)
    const float* norm1_w  = (const float*)d_in[2];
    const float* norm1_b  = (const float*)d_in[3];
    const float* in_proj_w= (const float*)d_in[4];
    const float* in_proj_b= (const float*)d_in[5];
    const float* out_w    = (const float*)d_in[6];
    const float* out_b    = (const float*)d_in[7];
    const float* norm2_w  = (const float*)d_in[8];
    const float* norm2_b  = (const float*)d_in[9];
    const float* ffn_w1   = (const float*)d_in[10];
    const float* ffn_b1   = (const float*)d_in[11];
    const float* ffn_w2   = (const float*)d_in[12];
    const float* ffn_b2   = (const float*)d_in[13];

    __half *h16, *qkv, *o16, *h2, *ffn, *wq, *wo, *w1, *w2;
    float* x1;
    cudaGetSymbolAddress((void**)&h16, g_h16);
    cudaGetSymbolAddress((void**)&qkv, g_qkv);
    cudaGetSymbolAddress((void**)&o16, g_o16);
    cudaGetSymbolAddress((void**)&x1,  g_x1);
    cudaGetSymbolAddress((void**)&h2,  g_h2);
    cudaGetSymbolAddress((void**)&ffn, g_ffn);
    cudaGetSymbolAddress((void**)&wq,  g_wqkv);
    cudaGetSymbolAddress((void**)&wo,  g_wout);
    cudaGetSymbolAddress((void**)&w1,  g_w1);
    cudaGetSymbolAddress((void**)&w2,  g_w2);

    cudaFuncSetAttribute(gemm_mma<0>, cudaFuncAttributeMaxDynamicSharedMemorySize, GSMEM);
    cudaFuncSetAttribute(gemm_mma<1>, cudaFuncAttributeMaxDynamicSharedMemorySize, GSMEM);
    cudaFuncSetAttribute(gemm_mma<2>, cudaFuncAttributeMaxDynamicSharedMemorySize, GSMEM);

    // weight conversion fp32 -> fp16
    f2h_kernel<<<4608, 256>>>(in_proj_w, wq, 3 * DD * DD);
    f2h_kernel<<<2304, 256>>>(out_w,     wo, DD * DD);
    f2h_kernel<<<4608, 256>>>(ffn_w1,    w1, 4 * DD * DD);
    f2h_kernel<<<4608, 256>>>(ffn_w2,    w2, DD * 4 * DD);

    // LN1
    ln_kernel<<<(unsigned)TOK, 192>>>(x, norm1_w, norm1_b, h16);

    // QKV = LN1 @ Wqkv^T + b
    gemm_mma<0><<<dim3(3 * DD / 128, (unsigned)(TOK / 128)), 256, GSMEM>>>(
        h16, wq, in_proj_b, nullptr, qkv, DD, 3 * DD);

    // cross-view attention: (B*P*H)/4 warps-per-block groups
    attn_kernel<<<(BD * PP * HH) / 4, 128>>>(qkv, o16);

    // out proj + residual -> x1
    gemm_mma<2><<<dim3(DD / 128, (unsigned)(TOK / 128)), 256, GSMEM>>>(
        o16, wo, out_b, x, x1, DD, DD);

    // LN2
    ln_kernel<<<(unsigned)TOK, 192>>>(x1, norm2_w, norm2_b, h2);

    // FFN1 + exact GELU
    gemm_mma<1><<<dim3(4 * DD / 128, (unsigned)(TOK / 128)), 256, GSMEM>>>(
        h2, w1, ffn_b1, nullptr, ffn, DD, 4 * DD);

    // FFN2 + residual -> d_out (fp32)
    gemm_mma<2><<<dim3(DD / 128, (unsigned)(TOK / 128)), 256, GSMEM>>>(
        ffn, w2, ffn_b2, x1, (float*)d_out, 4 * DD, DD);

    (void)in_sizes; (void)n_in; (void)out_size;
}